// round 1
// baseline (speedup 1.0000x reference)
#include <cuda_runtime.h>
#include <math.h>

#define N 16384
#define HID 256
#define MI 128
#define NEDGE (N*4)

// ---------------- scratch (device globals; no allocation allowed) ----------
__device__ float g_p1[(size_t)N*MI];
__device__ float g_p2[(size_t)N*MI];
__device__ float g_rowsum1[N];   // sum_j exp(<p1_i,p2_j>/T)
__device__ float g_rowsum2[N];   // sum_j exp(<p2_i,p1_j>/T) == colsum of dir-1 matrix
__device__ float g_possum1[N];
__device__ float g_possum2[N];
__device__ float g_spos1[N];
__device__ float g_spos2[N];
__device__ float g_cnt[N];

// ---------------- zero-init stats ----------------
__global__ void zero_kernel() {
    int i = blockIdx.x*blockDim.x + threadIdx.x;
    if (i < N) {
        g_rowsum1[i]=0.f; g_rowsum2[i]=0.f;
        g_possum1[i]=0.f; g_possum2[i]=0.f;
        g_spos1[i]=0.f;   g_spos2[i]=0.f;
        g_cnt[i]=0.f;
    }
}

// ---------------- projection: p = l2norm(relu(h@W + b)) ----------------
// 8 rows per block, 128 threads; thread j owns output column j for all 8 rows.
#define PROJ_ROWS 8
__global__ void proj_kernel(const float* __restrict__ h1, const float* __restrict__ h2,
                            const float* __restrict__ W, const float* __restrict__ bias) {
    int row0 = blockIdx.x * PROJ_ROWS;
    const float* h; float* p;
    if (row0 < N) { h = h1 + (size_t)row0*HID; p = g_p1 + (size_t)row0*MI; }
    else          { h = h2 + (size_t)(row0-N)*HID; p = g_p2 + (size_t)(row0-N)*MI; }

    __shared__ __align__(16) float sh[PROJ_ROWS][HID];
    int j = threadIdx.x; // 0..127
    for (int idx = j; idx < PROJ_ROWS*HID; idx += 128)
        ((float*)sh)[idx] = h[idx];
    __syncthreads();

    float acc[PROJ_ROWS];
    float bj = bias[j];
    #pragma unroll
    for (int r = 0; r < PROJ_ROWS; r++) acc[r] = bj;

    for (int k = 0; k < HID; k += 4) {
        float w0 = W[(k+0)*MI + j];
        float w1 = W[(k+1)*MI + j];
        float w2 = W[(k+2)*MI + j];
        float w3 = W[(k+3)*MI + j];
        #pragma unroll
        for (int r = 0; r < PROJ_ROWS; r++) {
            float4 hv = *(const float4*)&sh[r][k];   // broadcast across warp
            acc[r] = fmaf(hv.x, w0, acc[r]);
            acc[r] = fmaf(hv.y, w1, acc[r]);
            acc[r] = fmaf(hv.z, w2, acc[r]);
            acc[r] = fmaf(hv.w, w3, acc[r]);
        }
    }

    __shared__ float red[PROJ_ROWS][4];
    #pragma unroll
    for (int r = 0; r < PROJ_ROWS; r++) {
        acc[r] = fmaxf(acc[r], 0.f);
        float sq = acc[r]*acc[r];
        #pragma unroll
        for (int o = 16; o > 0; o >>= 1) sq += __shfl_down_sync(0xffffffffu, sq, o);
        if ((j & 31) == 0) red[r][j >> 5] = sq;
    }
    __syncthreads();
    #pragma unroll
    for (int r = 0; r < PROJ_ROWS; r++) {
        float n2 = red[r][0] + red[r][1] + red[r][2] + red[r][3];
        p[(size_t)r*MI + j] = acc[r] * rsqrtf(n2);
    }
}

// ---------------- big kernel: exp(sim) row-sums + col-sums in one pass -----
// 128x128 output tile per CTA, 256 threads, 8x8 micro-tiles, K=128 in smem.
#define TS  128
#define TST 132   // padded smem row stride (floats); keeps float4 alignment
#define SIM_SMEM (2u*TST*MI*sizeof(float))   // 135168 bytes

__global__ void __launch_bounds__(256,1) sim_kernel() {
    extern __shared__ float smem[];
    float* As = smem;            // As[k*TST + i]  (k-major)
    float* Bs = smem + TST*MI;   // Bs[k*TST + j]
    int tid = threadIdx.x;
    int tx = tid & 15, ty = tid >> 4;
    int i0 = blockIdx.y * TS, j0 = blockIdx.x * TS;

    const float* A = g_p1 + (size_t)i0*MI;
    const float* B = g_p2 + (size_t)j0*MI;
    for (int idx = tid; idx < TS*MI; idx += 256) {
        int i = idx >> 7, k = idx & 127;
        As[k*TST + i] = A[idx];
        Bs[k*TST + i] = B[idx];
    }
    __syncthreads();

    float acc[8][8];
    #pragma unroll
    for (int r = 0; r < 8; r++)
        #pragma unroll
        for (int c = 0; c < 8; c++) acc[r][c] = 0.f;

    int ao = ty*8, bo = tx*8;
    #pragma unroll 2
    for (int k = 0; k < MI; k++) {
        float4 a0 = *(const float4*)&As[k*TST + ao];
        float4 a1 = *(const float4*)&As[k*TST + ao + 4];
        float4 b0 = *(const float4*)&Bs[k*TST + bo];
        float4 b1 = *(const float4*)&Bs[k*TST + bo + 4];
        float a[8] = {a0.x,a0.y,a0.z,a0.w,a1.x,a1.y,a1.z,a1.w};
        float b[8] = {b0.x,b0.y,b0.z,b0.w,b1.x,b1.y,b1.z,b1.w};
        #pragma unroll
        for (int r = 0; r < 8; r++)
            #pragma unroll
            for (int c = 0; c < 8; c++)
                acc[r][c] = fmaf(a[r], b[c], acc[r][c]);
    }

    // exp + per-thread partial row/col sums (s = dot/T = 2*dot; |s|<=2, safe)
    float cs[8];
    #pragma unroll
    for (int c = 0; c < 8; c++) cs[c] = 0.f;
    float rs[8];
    #pragma unroll
    for (int r = 0; r < 8; r++) {
        float rsum = 0.f;
        #pragma unroll
        for (int c = 0; c < 8; c++) {
            float v = __expf(2.0f * acc[r][c]);
            rsum += v;
            cs[c] += v;
        }
        rs[r] = rsum;
    }

    // row sums: reduce across the 16 tx lanes (half-warp segments)
    #pragma unroll
    for (int r = 0; r < 8; r++) {
        #pragma unroll
        for (int o = 8; o > 0; o >>= 1)
            rs[r] += __shfl_down_sync(0xffffffffu, rs[r], o, 16);
    }
    if (tx == 0) {
        #pragma unroll
        for (int r = 0; r < 8; r++)
            atomicAdd(&g_rowsum1[i0 + ty*8 + r], rs[r]);
    }

    // col sums: via smem (reuse tile space), reduce across ty
    __syncthreads();
    float* red = smem;  // [16][128]
    #pragma unroll
    for (int c = 0; c < 8; c++) red[ty*128 + tx*8 + c] = cs[c];
    __syncthreads();
    if (tid < 128) {
        float s = 0.f;
        #pragma unroll
        for (int t = 0; t < 16; t++) s += red[t*128 + tid];
        atomicAdd(&g_rowsum2[j0 + tid], s);
    }
}

// ---------------- positives: warp per edge, both directions ----------------
__global__ void pos_kernel(const int* __restrict__ pr, const int* __restrict__ pc) {
    int e = (blockIdx.x * blockDim.x + threadIdx.x) >> 5;
    int lane = threadIdx.x & 31;
    if (e >= NEDGE) return;
    int r = pr[e], c = pc[e];
    const float4* p1r = (const float4*)(g_p1 + (size_t)r*MI);
    const float4* p2r = (const float4*)(g_p2 + (size_t)r*MI);
    const float4* p1c = (const float4*)(g_p1 + (size_t)c*MI);
    const float4* p2c = (const float4*)(g_p2 + (size_t)c*MI);
    float4 a1 = p1r[lane], b2 = p2c[lane];
    float4 a2 = p2r[lane], b1 = p1c[lane];
    float d1 = a1.x*b2.x + a1.y*b2.y + a1.z*b2.z + a1.w*b2.w;
    float d2 = a2.x*b1.x + a2.y*b1.y + a2.z*b1.z + a2.w*b1.w;
    #pragma unroll
    for (int o = 16; o > 0; o >>= 1) {
        d1 += __shfl_down_sync(0xffffffffu, d1, o);
        d2 += __shfl_down_sync(0xffffffffu, d2, o);
    }
    if (lane == 0) {
        float s1 = 2.0f*d1, s2 = 2.0f*d2;
        atomicAdd(&g_spos1[r],   s1);
        atomicAdd(&g_possum1[r], __expf(s1));
        atomicAdd(&g_spos2[r],   s2);
        atomicAdd(&g_possum2[r], __expf(s2));
        atomicAdd(&g_cnt[r],     1.0f);
    }
}

// ---------------- final loss reduction ----------------
// per_row_d = spos_d/cnt - log(rowsum_d - possum_d);  loss = -(1/(2N)) sum(per1+per2)
__global__ void loss_kernel(float* out) {
    float acc = 0.f;
    for (int i = threadIdx.x; i < N; i += blockDim.x) {
        float cnt = g_cnt[i];
        float inv = (cnt > 0.f) ? (1.0f/cnt) : 0.f;
        float per1 = g_spos1[i]*inv - logf(g_rowsum1[i] - g_possum1[i]);
        float per2 = g_spos2[i]*inv - logf(g_rowsum2[i] - g_possum2[i]);
        acc += per1 + per2;
    }
    __shared__ float red[8];
    #pragma unroll
    for (int o = 16; o > 0; o >>= 1) acc += __shfl_down_sync(0xffffffffu, acc, o);
    if ((threadIdx.x & 31) == 0) red[threadIdx.x >> 5] = acc;
    __syncthreads();
    if (threadIdx.x == 0) {
        float t = 0.f;
        #pragma unroll
        for (int w = 0; w < 8; w++) t += red[w];
        out[0] = -0.5f * t / (float)N;
    }
}

// ---------------- launch ----------------
extern "C" void kernel_launch(void* const* d_in, const int* in_sizes, int n_in,
                              void* d_out, int out_size) {
    const float* h1 = (const float*)d_in[0];
    const float* h2 = (const float*)d_in[1];
    const float* W  = (const float*)d_in[2];
    const float* b  = (const float*)d_in[3];
    const int*   pr = (const int*)d_in[4];
    const int*   pc = (const int*)d_in[5];
    float* out = (float*)d_out;

    zero_kernel<<<(N + 255)/256, 256>>>();
    proj_kernel<<<(2*N)/PROJ_ROWS, 128>>>(h1, h2, W, b);

    cudaFuncSetAttribute(sim_kernel, cudaFuncAttributeMaxDynamicSharedMemorySize,
                         (int)SIM_SMEM);
    dim3 g(N/TS, N/TS);
    sim_kernel<<<g, 256, SIM_SMEM>>>();

    pos_kernel<<<(NEDGE*32)/256, 256>>>(pr, pc);
    loss_kernel<<<1, 256>>>(out);
}

// round 4
// speedup vs baseline: 3.2287x; 3.2287x over previous
#include <cuda_runtime.h>
#include <cuda_bf16.h>
#include <mma.h>
#include <math.h>

using namespace nvcuda;

#define N 16384
#define HID 256
#define MI 128
#define NEDGE (N*4)

// ---------------- scratch (device globals; no allocation allowed) ----------
__device__ float g_p1[(size_t)N*MI];
__device__ float g_p2[(size_t)N*MI];
__device__ __nv_bfloat16 g_p1h[(size_t)N*MI];
__device__ __nv_bfloat16 g_p2h[(size_t)N*MI];
__device__ float g_rowsum1[N];
__device__ float g_rowsum2[N];
__device__ float g_possum1[N];
__device__ float g_possum2[N];
__device__ float g_spos1[N];
__device__ float g_spos2[N];

// ---------------- zero-init stats ----------------
__global__ void zero_kernel() {
    int i = blockIdx.x * blockDim.x + threadIdx.x;
    if (i < N) {
        g_rowsum1[i] = 0.f;
        g_rowsum2[i] = 0.f;
        g_possum1[i] = 0.f;
        g_possum2[i] = 0.f;
        g_spos1[i] = 0.f;
        g_spos2[i] = 0.f;
    }
}

// ============ projection (tf32 wmma): p = l2norm(relu(h@W + b)) =============
// CTA: 16 rows x 128 cols, 128 threads = 4 warps; warp w owns col range w*32.
#define PJ_LD 132

__global__ void __launch_bounds__(128, 1) proj_kernel(
        const float* __restrict__ h1, const float* __restrict__ h2,
        const float* __restrict__ W, const float* __restrict__ bias) {
    __shared__ float cs[16 * PJ_LD];
    __shared__ float rowsq[16];

    int tid = threadIdx.x;
    int warp = tid >> 5;
    int row0 = blockIdx.x * 16;

    const float* hsrc;
    float* pdst;
    __nv_bfloat16* phdst;
    if (row0 < N) {
        hsrc = h1 + (size_t)row0 * HID;
        pdst = g_p1 + (size_t)row0 * MI;
        phdst = g_p1h + (size_t)row0 * MI;
    } else {
        int r0 = row0 - N;
        hsrc = h2 + (size_t)r0 * HID;
        pdst = g_p2 + (size_t)r0 * MI;
        phdst = g_p2h + (size_t)r0 * MI;
    }

    wmma::fragment<wmma::accumulator, 16, 16, 8, float> acc0;
    wmma::fragment<wmma::accumulator, 16, 16, 8, float> acc1;
    wmma::fill_fragment(acc0, 0.0f);
    wmma::fill_fragment(acc1, 0.0f);

    int n0 = warp * 32;
    for (int k = 0; k < HID; k += 8) {
        wmma::fragment<wmma::matrix_a, 16, 16, 8, wmma::precision::tf32,
                       wmma::row_major> af;
        wmma::load_matrix_sync(af, hsrc + k, HID);
        for (int i = 0; i < af.num_elements; i++)
            af.x[i] = wmma::__float_to_tf32(af.x[i]);

        wmma::fragment<wmma::matrix_b, 16, 16, 8, wmma::precision::tf32,
                       wmma::row_major> bf0;
        wmma::fragment<wmma::matrix_b, 16, 16, 8, wmma::precision::tf32,
                       wmma::row_major> bf1;
        wmma::load_matrix_sync(bf0, W + (size_t)k * MI + n0, MI);
        wmma::load_matrix_sync(bf1, W + (size_t)k * MI + n0 + 16, MI);
        for (int i = 0; i < bf0.num_elements; i++)
            bf0.x[i] = wmma::__float_to_tf32(bf0.x[i]);
        for (int i = 0; i < bf1.num_elements; i++)
            bf1.x[i] = wmma::__float_to_tf32(bf1.x[i]);

        wmma::mma_sync(acc0, af, bf0, acc0);
        wmma::mma_sync(acc1, af, bf1, acc1);
    }

    wmma::store_matrix_sync(cs + n0, acc0, PJ_LD, wmma::mem_row_major);
    wmma::store_matrix_sync(cs + n0 + 16, acc1, PJ_LD, wmma::mem_row_major);
    if (tid < 16) rowsq[tid] = 0.0f;
    __syncthreads();

    // thread t: row = t>>3, 16 cols starting at (t&7)*16
    int r = tid >> 3;
    int c0 = (tid & 7) * 16;
    float vals[16];
    float sq = 0.0f;
    for (int c = 0; c < 16; c++) {
        float v = cs[r * PJ_LD + c0 + c] + bias[c0 + c];
        v = fmaxf(v, 0.0f);
        vals[c] = v;
        sq += v * v;
    }
    atomicAdd(&rowsq[r], sq);
    __syncthreads();

    float s = rsqrtf(rowsq[r]);
    for (int c = 0; c < 16; c++) {
        float o = vals[c] * s;
        pdst[(size_t)r * MI + c0 + c] = o;
        phdst[(size_t)r * MI + c0 + c] = __float2bfloat16_rn(o);
    }
}

// ============ sim kernel (bf16 wmma): exp(dot/T) row + col sums =============
// CTA: 256 threads = 8 warps; 128x128 output tile, K=128 resident in smem.
// Warp w owns output rows w*16 .. w*16+16 (all 128 cols).
#define SLD 136            // smem row stride in bf16 elements (272 bytes)
#define STG 20             // staging row stride in floats
#define SIM_SMEM (2*128*SLD*2 + 8*16*STG*4 + 8*128*4)

__global__ void __launch_bounds__(256, 1) sim_kernel() {
    extern __shared__ unsigned char dynsm[];
    __nv_bfloat16* As = (__nv_bfloat16*)dynsm;
    __nv_bfloat16* Bs = As + 128 * SLD;
    float* stage = (float*)(Bs + 128 * SLD);
    float* colwarp = stage + 8 * 16 * STG;

    int tid = threadIdx.x;
    int warp = tid >> 5;
    int lane = tid & 31;
    int i0 = blockIdx.y * 128;
    int j0 = blockIdx.x * 128;

    // cooperative load of A (rows i0..) and B (rows j0..) into padded smem
    const uint4* srcA = (const uint4*)(g_p1h + (size_t)i0 * MI);
    const uint4* srcB = (const uint4*)(g_p2h + (size_t)j0 * MI);
    for (int idx = tid; idx < 2048; idx += 256) {
        int r = idx >> 4;
        int ch = idx & 15;
        *(uint4*)(As + r * SLD + ch * 8) = srcA[idx];
        *(uint4*)(Bs + r * SLD + ch * 8) = srcB[idx];
    }
    for (int c = lane; c < 128; c += 32) colwarp[warp * 128 + c] = 0.0f;
    __syncthreads();

    // A fragments for this warp's 16 rows, all 8 k-steps
    wmma::fragment<wmma::matrix_a, 16, 16, 16, __nv_bfloat16,
                   wmma::row_major> af[8];
    for (int k = 0; k < 8; k++)
        wmma::load_matrix_sync(af[k], As + warp * 16 * SLD + k * 16, SLD);

    float* mystage = stage + warp * 16 * STG;
    float rowsum = 0.0f;

    for (int jt = 0; jt < 8; jt++) {
        wmma::fragment<wmma::accumulator, 16, 16, 16, float> acc;
        wmma::fill_fragment(acc, 0.0f);
        for (int k = 0; k < 8; k++) {
            wmma::fragment<wmma::matrix_b, 16, 16, 16, __nv_bfloat16,
                           wmma::col_major> bf;
            wmma::load_matrix_sync(bf, Bs + jt * 16 * SLD + k * 16, SLD);
            wmma::mma_sync(acc, af[k], bf, acc);
        }
        wmma::store_matrix_sync(mystage, acc, STG, wmma::mem_row_major);
        __syncwarp();

        // pass 1 (rows): lane covers row (lane&15), 8 cols at (lane>>4)*8.
        // computes exp, writes it back, accumulates row partials.
        {
            int r = lane & 15;
            int cb = (lane >> 4) * 8;
            float part = 0.0f;
            for (int c = 0; c < 8; c++) {
                float e = __expf(2.0f * mystage[r * STG + cb + c]);
                mystage[r * STG + cb + c] = e;
                part += e;
            }
            part += __shfl_xor_sync(0xffffffffu, part, 16);
            rowsum += part;   // every lane holds the full row total now
        }
        __syncwarp();

        // pass 2 (cols): lane covers col (lane&15), 8 rows at (lane>>4)*8
        {
            int c = lane & 15;
            int rb = (lane >> 4) * 8;
            float part = 0.0f;
            for (int r2 = 0; r2 < 8; r2++)
                part += mystage[(rb + r2) * STG + c];
            part += __shfl_xor_sync(0xffffffffu, part, 16);
            if (lane < 16) colwarp[warp * 128 + jt * 16 + c] += part;
        }
        __syncwarp();
    }

    if (lane < 16)
        atomicAdd(&g_rowsum1[i0 + warp * 16 + lane], rowsum);

    __syncthreads();
    if (tid < 128) {
        float s = 0.0f;
        for (int w = 0; w < 8; w++) s += colwarp[w * 128 + tid];
        atomicAdd(&g_rowsum2[j0 + tid], s);
    }
}

// ---------------- positives: warp per edge, both directions (fp32) ---------
__global__ void pos_kernel(const int* __restrict__ pr, const int* __restrict__ pc) {
    int e = (blockIdx.x * blockDim.x + threadIdx.x) >> 5;
    int lane = threadIdx.x & 31;
    if (e >= NEDGE) return;
    int r = pr[e];
    int c = pc[e];
    const float4* p1r = (const float4*)(g_p1 + (size_t)r * MI);
    const float4* p2r = (const float4*)(g_p2 + (size_t)r * MI);
    const float4* p1c = (const float4*)(g_p1 + (size_t)c * MI);
    const float4* p2c = (const float4*)(g_p2 + (size_t)c * MI);
    float4 a1 = p1r[lane];
    float4 b2 = p2c[lane];
    float4 a2 = p2r[lane];
    float4 b1 = p1c[lane];
    float d1 = a1.x * b2.x + a1.y * b2.y + a1.z * b2.z + a1.w * b2.w;
    float d2 = a2.x * b1.x + a2.y * b1.y + a2.z * b1.z + a2.w * b1.w;
    for (int o = 16; o > 0; o >>= 1) {
        d1 += __shfl_down_sync(0xffffffffu, d1, o);
        d2 += __shfl_down_sync(0xffffffffu, d2, o);
    }
    if (lane == 0) {
        float s1 = 2.0f * d1;
        float s2 = 2.0f * d2;
        atomicAdd(&g_spos1[r], s1);
        atomicAdd(&g_possum1[r], __expf(s1));
        atomicAdd(&g_spos2[r], s2);
        atomicAdd(&g_possum2[r], __expf(s2));
    }
}

// ---------------- final loss reduction ----------------
__global__ void loss_kernel(float* out) {
    float acc = 0.f;
    const float invcnt = 0.25f;   // exactly 4 positives per row by construction
    for (int i = threadIdx.x; i < N; i += blockDim.x) {
        float per1 = g_spos1[i] * invcnt - logf(g_rowsum1[i] - g_possum1[i]);
        float per2 = g_spos2[i] * invcnt - logf(g_rowsum2[i] - g_possum2[i]);
        acc += per1 + per2;
    }
    __shared__ float red[8];
    for (int o = 16; o > 0; o >>= 1)
        acc += __shfl_down_sync(0xffffffffu, acc, o);
    if ((threadIdx.x & 31) == 0) red[threadIdx.x >> 5] = acc;
    __syncthreads();
    if (threadIdx.x == 0) {
        float t = 0.f;
        for (int w = 0; w < 8; w++) t += red[w];
        out[0] = -0.5f * t / (float)N;
    }
}

// ---------------- launch ----------------
extern "C" void kernel_launch(void* const* d_in, const int* in_sizes, int n_in,
                              void* d_out, int out_size) {
    const float* h1 = (const float*)d_in[0];
    const float* h2 = (const float*)d_in[1];
    const float* W  = (const float*)d_in[2];
    const float* b  = (const float*)d_in[3];
    const int*   pr = (const int*)d_in[4];
    const int*   pc = (const int*)d_in[5];
    float* out = (float*)d_out;

    zero_kernel<<<(N + 255) / 256, 256>>>();

    proj_kernel<<<(2 * N) / 16, 128>>>(h1, h2, W, b);

    cudaFuncSetAttribute(sim_kernel,
                         cudaFuncAttributeMaxDynamicSharedMemorySize, SIM_SMEM);
    dim3 simgrid(N / 128, N / 128);
    sim_kernel<<<simgrid, 256, SIM_SMEM>>>();

    pos_kernel<<<(NEDGE * 32) / 256, 256>>>(pr, pc);
    loss_kernel<<<1, 256>>>(out);
}

// round 5
// speedup vs baseline: 3.6123x; 1.1188x over previous
#include <cuda_runtime.h>
#include <cuda_bf16.h>
#include <mma.h>
#include <math.h>

using namespace nvcuda;

#define N 16384
#define HID 256
#define MI 128
#define NEDGE (N*4)

// ---------------- scratch (device globals; no allocation allowed) ----------
__device__ float g_p1[(size_t)N*MI];
__device__ float g_p2[(size_t)N*MI];
__device__ __nv_bfloat16 g_p1h[(size_t)N*MI];
__device__ __nv_bfloat16 g_p2h[(size_t)N*MI];
__device__ float g_rowsum1[N];
__device__ float g_rowsum2[N];
__device__ float g_possum1[N];
__device__ float g_possum2[N];
__device__ float g_spos1[N];
__device__ float g_spos2[N];

// ---------------- zero-init stats ----------------
__global__ void zero_kernel() {
    int i = blockIdx.x * blockDim.x + threadIdx.x;
    if (i < N) {
        g_rowsum1[i] = 0.f;
        g_rowsum2[i] = 0.f;
        g_possum1[i] = 0.f;
        g_possum2[i] = 0.f;
        g_spos1[i] = 0.f;
        g_spos2[i] = 0.f;
    }
}

// ============ projection (tf32 wmma): p = l2norm(relu(h@W + b)) =============
// CTA: 16 rows x 128 cols, 128 threads = 4 warps; warp w owns col range w*32.
#define PJ_LD 132

__global__ void __launch_bounds__(128, 1) proj_kernel(
        const float* __restrict__ h1, const float* __restrict__ h2,
        const float* __restrict__ W, const float* __restrict__ bias) {
    __shared__ float cs[16 * PJ_LD];
    __shared__ float rowsq[16];

    int tid = threadIdx.x;
    int warp = tid >> 5;
    int row0 = blockIdx.x * 16;

    const float* hsrc;
    float* pdst;
    __nv_bfloat16* phdst;
    if (row0 < N) {
        hsrc = h1 + (size_t)row0 * HID;
        pdst = g_p1 + (size_t)row0 * MI;
        phdst = g_p1h + (size_t)row0 * MI;
    } else {
        int r0 = row0 - N;
        hsrc = h2 + (size_t)r0 * HID;
        pdst = g_p2 + (size_t)r0 * MI;
        phdst = g_p2h + (size_t)r0 * MI;
    }

    wmma::fragment<wmma::accumulator, 16, 16, 8, float> acc0;
    wmma::fragment<wmma::accumulator, 16, 16, 8, float> acc1;
    wmma::fill_fragment(acc0, 0.0f);
    wmma::fill_fragment(acc1, 0.0f);

    int n0 = warp * 32;
    for (int k = 0; k < HID; k += 8) {
        wmma::fragment<wmma::matrix_a, 16, 16, 8, wmma::precision::tf32,
                       wmma::row_major> af;
        wmma::load_matrix_sync(af, hsrc + k, HID);
        for (int i = 0; i < af.num_elements; i++)
            af.x[i] = wmma::__float_to_tf32(af.x[i]);

        wmma::fragment<wmma::matrix_b, 16, 16, 8, wmma::precision::tf32,
                       wmma::row_major> bf0;
        wmma::fragment<wmma::matrix_b, 16, 16, 8, wmma::precision::tf32,
                       wmma::row_major> bf1;
        wmma::load_matrix_sync(bf0, W + (size_t)k * MI + n0, MI);
        wmma::load_matrix_sync(bf1, W + (size_t)k * MI + n0 + 16, MI);
        for (int i = 0; i < bf0.num_elements; i++)
            bf0.x[i] = wmma::__float_to_tf32(bf0.x[i]);
        for (int i = 0; i < bf1.num_elements; i++)
            bf1.x[i] = wmma::__float_to_tf32(bf1.x[i]);

        wmma::mma_sync(acc0, af, bf0, acc0);
        wmma::mma_sync(acc1, af, bf1, acc1);
    }

    wmma::store_matrix_sync(cs + n0, acc0, PJ_LD, wmma::mem_row_major);
    wmma::store_matrix_sync(cs + n0 + 16, acc1, PJ_LD, wmma::mem_row_major);
    if (tid < 16) rowsq[tid] = 0.0f;
    __syncthreads();

    int r = tid >> 3;
    int c0 = (tid & 7) * 16;
    float vals[16];
    float sq = 0.0f;
    for (int c = 0; c < 16; c++) {
        float v = cs[r * PJ_LD + c0 + c] + bias[c0 + c];
        v = fmaxf(v, 0.0f);
        vals[c] = v;
        sq += v * v;
    }
    atomicAdd(&rowsq[r], sq);
    __syncthreads();

    float s = rsqrtf(rowsq[r]);
    for (int c = 0; c < 16; c++) {
        float o = vals[c] * s;
        pdst[(size_t)r * MI + c0 + c] = o;
        phdst[(size_t)r * MI + c0 + c] = __float2bfloat16_rn(o);
    }
}

// ============ sim kernel (bf16 wmma): exp(dot/T) row + col sums =============
// CTA: 256 threads = 8 warps (4M x 2N); 128x128 tile, K=128 resident.
// Warp (wm, wn): rows wm*32..+32, cols wn*64..+64. 8 independent accumulators.
#define SLD 136            // A/B smem row stride in bf16 elements (272 bytes)
#define STW 68             // staging row stride in floats
#define SIM_SMEM (2*128*SLD*2 + 8*64*4)   // 69632 (A/B, aliased by staging) + colpriv

__global__ void __launch_bounds__(256, 2) sim_kernel() {
    extern __shared__ unsigned char dynsm[];
    __nv_bfloat16* As = (__nv_bfloat16*)dynsm;
    __nv_bfloat16* Bs = As + 128 * SLD;
    float* stgbase = (float*)dynsm;                  // aliases As/Bs after mainloop
    float* colpriv = (float*)dynsm + 8 * 32 * STW;   // 8 warps x 64 cols
    __shared__ float rowred[128];

    int tid = threadIdx.x;
    int warp = tid >> 5;
    int lane = tid & 31;
    int wm = warp >> 1;          // 0..3  (rows wm*32)
    int wn = warp & 1;           // 0..1  (cols wn*64)
    int i0 = blockIdx.y * 128;
    int j0 = blockIdx.x * 128;

    const uint4* srcA = (const uint4*)(g_p1h + (size_t)i0 * MI);
    const uint4* srcB = (const uint4*)(g_p2h + (size_t)j0 * MI);
    for (int idx = tid; idx < 2048; idx += 256) {
        int r = idx >> 4;
        int ch = idx & 15;
        *(uint4*)(As + r * SLD + ch * 8) = srcA[idx];
        *(uint4*)(Bs + r * SLD + ch * 8) = srcB[idx];
    }
    if (tid < 128) rowred[tid] = 0.0f;
    __syncthreads();

    wmma::fragment<wmma::accumulator, 16, 16, 16, float> acc0[4];
    wmma::fragment<wmma::accumulator, 16, 16, 16, float> acc1[4];
    #pragma unroll
    for (int nt = 0; nt < 4; nt++) {
        wmma::fill_fragment(acc0[nt], 0.0f);
        wmma::fill_fragment(acc1[nt], 0.0f);
    }

    const __nv_bfloat16* arow0 = As + (wm * 32) * SLD;
    const __nv_bfloat16* arow1 = As + (wm * 32 + 16) * SLD;
    const __nv_bfloat16* bbase = Bs + (wn * 64) * SLD;

    #pragma unroll
    for (int k = 0; k < 8; k++) {
        wmma::fragment<wmma::matrix_a, 16, 16, 16, __nv_bfloat16,
                       wmma::row_major> af0;
        wmma::fragment<wmma::matrix_a, 16, 16, 16, __nv_bfloat16,
                       wmma::row_major> af1;
        wmma::load_matrix_sync(af0, arow0 + k * 16, SLD);
        wmma::load_matrix_sync(af1, arow1 + k * 16, SLD);
        #pragma unroll
        for (int nt = 0; nt < 4; nt++) {
            wmma::fragment<wmma::matrix_b, 16, 16, 16, __nv_bfloat16,
                           wmma::col_major> bf;
            wmma::load_matrix_sync(bf, bbase + nt * 16 * SLD + k * 16, SLD);
            wmma::mma_sync(acc0[nt], af0, bf, acc0[nt]);
            wmma::mma_sync(acc1[nt], af1, bf, acc1[nt]);
        }
    }

    // exp in-register (elementwise fragment ops are layout-agnostic)
    #pragma unroll
    for (int nt = 0; nt < 4; nt++) {
        for (int e = 0; e < acc0[nt].num_elements; e++)
            acc0[nt].x[e] = __expf(2.0f * acc0[nt].x[e]);
        for (int e = 0; e < acc1[nt].num_elements; e++)
            acc1[nt].x[e] = __expf(2.0f * acc1[nt].x[e]);
    }

    // A/B smem is dead now; alias it as per-warp staging (32 x STW floats)
    __syncthreads();
    float* stg = stgbase + warp * 32 * STW;
    #pragma unroll
    for (int nt = 0; nt < 4; nt++) {
        wmma::store_matrix_sync(stg + nt * 16, acc0[nt], STW,
                                wmma::mem_row_major);
        wmma::store_matrix_sync(stg + 16 * STW + nt * 16, acc1[nt], STW,
                                wmma::mem_row_major);
    }
    __syncwarp();

    // row pass: lane owns local row = lane (32 rows), reads 64 floats
    {
        const float4* rp = (const float4*)(stg + lane * STW);
        float rs = 0.0f;
        #pragma unroll
        for (int q = 0; q < 16; q++) {
            float4 v = rp[q];
            rs += v.x + v.y + v.z + v.w;
        }
        atomicAdd(&rowred[wm * 32 + lane], rs);
    }

    // col pass: lane owns 2 cols (2*lane, 2*lane+1) of this warp's 64
    {
        int c2 = lane * 2;
        float s0 = 0.0f;
        float s1 = 0.0f;
        #pragma unroll
        for (int r2 = 0; r2 < 32; r2++) {
            const float* row = stg + r2 * STW;
            s0 += row[c2];
            s1 += row[c2 + 1];
        }
        colpriv[warp * 64 + c2] = s0;
        colpriv[warp * 64 + c2 + 1] = s1;
    }
    __syncthreads();

    if (tid < 128) {
        atomicAdd(&g_rowsum1[i0 + tid], rowred[tid]);
        int wnj = tid >> 6;
        int cj = tid & 63;
        float s = colpriv[(0 * 2 + wnj) * 64 + cj]
                + colpriv[(1 * 2 + wnj) * 64 + cj]
                + colpriv[(2 * 2 + wnj) * 64 + cj]
                + colpriv[(3 * 2 + wnj) * 64 + cj];
        atomicAdd(&g_rowsum2[j0 + tid], s);
    }
}

// ---------------- positives: warp per edge, both directions (fp32) ---------
__global__ void pos_kernel(const int* __restrict__ pr, const int* __restrict__ pc) {
    int e = (blockIdx.x * blockDim.x + threadIdx.x) >> 5;
    int lane = threadIdx.x & 31;
    if (e >= NEDGE) return;
    int r = pr[e];
    int c = pc[e];
    const float4* p1r = (const float4*)(g_p1 + (size_t)r * MI);
    const float4* p2r = (const float4*)(g_p2 + (size_t)r * MI);
    const float4* p1c = (const float4*)(g_p1 + (size_t)c * MI);
    const float4* p2c = (const float4*)(g_p2 + (size_t)c * MI);
    float4 a1 = p1r[lane];
    float4 b2 = p2c[lane];
    float4 a2 = p2r[lane];
    float4 b1 = p1c[lane];
    float d1 = a1.x * b2.x + a1.y * b2.y + a1.z * b2.z + a1.w * b2.w;
    float d2 = a2.x * b1.x + a2.y * b1.y + a2.z * b1.z + a2.w * b1.w;
    for (int o = 16; o > 0; o >>= 1) {
        d1 += __shfl_down_sync(0xffffffffu, d1, o);
        d2 += __shfl_down_sync(0xffffffffu, d2, o);
    }
    if (lane == 0) {
        float s1 = 2.0f * d1;
        float s2 = 2.0f * d2;
        atomicAdd(&g_spos1[r], s1);
        atomicAdd(&g_possum1[r], __expf(s1));
        atomicAdd(&g_spos2[r], s2);
        atomicAdd(&g_possum2[r], __expf(s2));
    }
}

// ---------------- final loss reduction ----------------
__global__ void loss_kernel(float* out) {
    float acc = 0.f;
    const float invcnt = 0.25f;   // exactly 4 positives per row by construction
    for (int i = threadIdx.x; i < N; i += blockDim.x) {
        float per1 = g_spos1[i] * invcnt - logf(g_rowsum1[i] - g_possum1[i]);
        float per2 = g_spos2[i] * invcnt - logf(g_rowsum2[i] - g_possum2[i]);
        acc += per1 + per2;
    }
    __shared__ float red[8];
    for (int o = 16; o > 0; o >>= 1)
        acc += __shfl_down_sync(0xffffffffu, acc, o);
    if ((threadIdx.x & 31) == 0) red[threadIdx.x >> 5] = acc;
    __syncthreads();
    if (threadIdx.x == 0) {
        float t = 0.f;
        for (int w = 0; w < 8; w++) t += red[w];
        out[0] = -0.5f * t / (float)N;
    }
}

// ---------------- launch ----------------
extern "C" void kernel_launch(void* const* d_in, const int* in_sizes, int n_in,
                              void* d_out, int out_size) {
    const float* h1 = (const float*)d_in[0];
    const float* h2 = (const float*)d_in[1];
    const float* W  = (const float*)d_in[2];
    const float* b  = (const float*)d_in[3];
    const int*   pr = (const int*)d_in[4];
    const int*   pc = (const int*)d_in[5];
    float* out = (float*)d_out;

    zero_kernel<<<(N + 255) / 256, 256>>>();

    proj_kernel<<<(2 * N) / 16, 128>>>(h1, h2, W, b);

    cudaFuncSetAttribute(sim_kernel,
                         cudaFuncAttributeMaxDynamicSharedMemorySize, SIM_SMEM);
    dim3 simgrid(N / 128, N / 128);
    sim_kernel<<<simgrid, 256, SIM_SMEM>>>();

    pos_kernel<<<(NEDGE * 32) / 256, 256>>>(pr, pc);
    loss_kernel<<<1, 256>>>(out);
}